// round 4
// baseline (speedup 1.0000x reference)
#include <cuda_runtime.h>
#include <cuda_bf16.h>
#include <math.h>

#define BATCH 64
#define SEQ   196
#define DIMC  768
#define HEADS 12
#define HD    64
#define QKV3  2304           // 3*DIMC
#define BN    (BATCH*SEQ)    // 12544
#define SCALE 0.125f         // HD^-0.5

// ---------------- scratch (no allocation allowed; __device__ globals) -------
__device__ float g_qkv[(size_t)BATCH * SEQ * QKV3];           // [BN, 2304]
__device__ float g_ao[(size_t)BATCH * SEQ * DIMC];            // [BN, 768]

// ---------------- tf32 helpers ----------------------------------------------
__device__ __forceinline__ unsigned f2tf32(float x) {
    unsigned u;
    asm volatile("cvt.rna.tf32.f32 %0, %1;" : "=r"(u) : "f"(x));
    return u;
}

__device__ __forceinline__ void mma_tf32(float (&d)[4], const unsigned (&a)[4],
                                         const unsigned (&b)[2]) {
    asm volatile(
        "mma.sync.aligned.m16n8k8.row.col.f32.tf32.tf32.f32 "
        "{%0,%1,%2,%3}, {%4,%5,%6,%7}, {%8,%9}, {%0,%1,%2,%3};\n"
        : "+f"(d[0]), "+f"(d[1]), "+f"(d[2]), "+f"(d[3])
        : "r"(a[0]), "r"(a[1]), "r"(a[2]), "r"(a[3]), "r"(b[0]), "r"(b[1]));
}

// ---------------- TF32 GEMM: C[M,N] = A[M,K] @ B[K,N] (+bias) ---------------
// 128x64 block tile, BK=32, 256 threads = 8 warps, warp tile 32x32 (2x4 mma).
// Software pipelined: register prefetch of next tile + ping-pong smem buffers.
#define TBM 128
#define TBN 64
#define TBK 32
#define AS_STRIDE 36
#define BS_STRIDE 72
#define A_WORDS (TBM * AS_STRIDE)      // 4608
#define B_WORDS (TBK * BS_STRIDE)      // 2304
#define GEMM_SMEM_BYTES ((A_WORDS + B_WORDS) * 2 * 4)   // 55296

__global__ __launch_bounds__(256)
void gemm_tf32_kernel(const float* __restrict__ A, const float* __restrict__ B,
                      const float* __restrict__ bias, float* __restrict__ C,
                      int M, int N, int K, int useBias)
{
    extern __shared__ unsigned gsm[];
    unsigned* Asb[2] = {gsm, gsm + A_WORDS};
    unsigned* Bsb[2] = {gsm + 2 * A_WORDS, gsm + 2 * A_WORDS + B_WORDS};

    const int tid  = threadIdx.x;
    const int lane = tid & 31;
    const int warp = tid >> 5;
    const int r    = lane >> 2;
    const int tq   = lane & 3;
    const int warpM = (warp & 3) * 32;
    const int warpN = (warp >> 2) * 32;

    const int n0 = blockIdx.x * TBN;
    const int m0 = blockIdx.y * TBM;

    // per-thread load coordinates
    const int a_row = tid >> 3;             // 0..31 (x4 -> 128 rows)
    const int a_kc  = (tid & 7) * 4;        // 0..28
    const int b_kk  = tid >> 4;             // 0..15 (x2 -> 32 rows)
    const int b_nn  = (tid & 15) * 4;       // 0..60

    float acc[2][4][4];
#pragma unroll
    for (int i = 0; i < 2; i++)
#pragma unroll
        for (int j = 0; j < 4; j++)
#pragma unroll
            for (int t = 0; t < 4; t++) acc[i][j][t] = 0.f;

    float4 a_reg[4];
    float4 b_reg[2];

    // ---- prologue: load tile 0, store to buffer 0
#pragma unroll
    for (int i = 0; i < 4; i++)
        a_reg[i] = *(const float4*)(A + (size_t)(m0 + a_row + i * 32) * K + a_kc);
#pragma unroll
    for (int i = 0; i < 2; i++)
        b_reg[i] = *(const float4*)(B + (size_t)(b_kk + i * 16) * N + n0 + b_nn);

#pragma unroll
    for (int i = 0; i < 4; i++) {
        unsigned* p = &Asb[0][(a_row + i * 32) * AS_STRIDE + a_kc];
        p[0] = f2tf32(a_reg[i].x); p[1] = f2tf32(a_reg[i].y);
        p[2] = f2tf32(a_reg[i].z); p[3] = f2tf32(a_reg[i].w);
    }
#pragma unroll
    for (int i = 0; i < 2; i++) {
        unsigned* p = &Bsb[0][(b_kk + i * 16) * BS_STRIDE + b_nn];
        p[0] = f2tf32(b_reg[i].x); p[1] = f2tf32(b_reg[i].y);
        p[2] = f2tf32(b_reg[i].z); p[3] = f2tf32(b_reg[i].w);
    }
    __syncthreads();

    const int nTiles = K / TBK;
    for (int t = 0; t < nTiles; t++) {
        const int c = t & 1;
        const unsigned* As = Asb[c];
        const unsigned* Bs = Bsb[c];
        const bool havNext = (t + 1 < nTiles);

        // ---- prefetch next tile into registers (latency hidden by compute)
        if (havNext) {
            const int k0 = (t + 1) * TBK;
#pragma unroll
            for (int i = 0; i < 4; i++)
                a_reg[i] = *(const float4*)(A + (size_t)(m0 + a_row + i * 32) * K + k0 + a_kc);
#pragma unroll
            for (int i = 0; i < 2; i++)
                b_reg[i] = *(const float4*)(B + (size_t)(k0 + b_kk + i * 16) * N + n0 + b_nn);
        }

        // ---- compute current buffer
#pragma unroll
        for (int ks = 0; ks < 4; ks++) {
            int kb = ks * 8;
            unsigned afrag[2][4];
#pragma unroll
            for (int mt = 0; mt < 2; mt++) {
                int rb = warpM + mt * 16;
                afrag[mt][0] = As[(rb + r)     * AS_STRIDE + kb + tq];
                afrag[mt][1] = As[(rb + r + 8) * AS_STRIDE + kb + tq];
                afrag[mt][2] = As[(rb + r)     * AS_STRIDE + kb + tq + 4];
                afrag[mt][3] = As[(rb + r + 8) * AS_STRIDE + kb + tq + 4];
            }
            unsigned bfrag[4][2];
#pragma unroll
            for (int nt = 0; nt < 4; nt++) {
                int cb = warpN + nt * 8;
                bfrag[nt][0] = Bs[(kb + tq)     * BS_STRIDE + cb + r];
                bfrag[nt][1] = Bs[(kb + tq + 4) * BS_STRIDE + cb + r];
            }
#pragma unroll
            for (int mt = 0; mt < 2; mt++)
#pragma unroll
                for (int nt = 0; nt < 4; nt++)
                    mma_tf32(acc[mt][nt], afrag[mt], bfrag[nt]);
        }

        // ---- store prefetched tile into other buffer, single barrier
        if (havNext) {
            unsigned* An = Asb[c ^ 1];
            unsigned* Bn = Bsb[c ^ 1];
#pragma unroll
            for (int i = 0; i < 4; i++) {
                unsigned* p = &An[(a_row + i * 32) * AS_STRIDE + a_kc];
                p[0] = f2tf32(a_reg[i].x); p[1] = f2tf32(a_reg[i].y);
                p[2] = f2tf32(a_reg[i].z); p[3] = f2tf32(a_reg[i].w);
            }
#pragma unroll
            for (int i = 0; i < 2; i++) {
                unsigned* p = &Bn[(b_kk + i * 16) * BS_STRIDE + b_nn];
                p[0] = f2tf32(b_reg[i].x); p[1] = f2tf32(b_reg[i].y);
                p[2] = f2tf32(b_reg[i].z); p[3] = f2tf32(b_reg[i].w);
            }
            __syncthreads();
        }
    }

    // ---- epilogue
#pragma unroll
    for (int mt = 0; mt < 2; mt++) {
#pragma unroll
        for (int nt = 0; nt < 4; nt++) {
            int row = m0 + warpM + mt * 16 + r;
            int col = n0 + warpN + nt * 8 + 2 * tq;
            float2 lo = make_float2(acc[mt][nt][0], acc[mt][nt][1]);
            float2 hi = make_float2(acc[mt][nt][2], acc[mt][nt][3]);
            if (useBias) {
                float2 bv = *(const float2*)(bias + col);
                lo.x += bv.x; lo.y += bv.y;
                hi.x += bv.x; hi.y += bv.y;
            }
            *(float2*)(C + (size_t)row * N + col)       = lo;
            *(float2*)(C + (size_t)(row + 8) * N + col) = hi;
        }
    }
}

// ---------------- fused attention: scores + softmax(+bias) + AV -------------
// One block per (b, h, q-half of 98 rows). 512 threads = 16 warps.
#define QS_OFF 0
#define KV_OFF 7616            // 112*68
#define S_OFF  22016           // 7616 + 14400
#define FUSED_SMEM_BYTES (45760 * 4)   // 183040

__global__ __launch_bounds__(512)
void fused_attn_kernel(const float* __restrict__ qkv,
                       const float* __restrict__ sa,
                       float* __restrict__ ao)
{
    extern __shared__ float sm[];
    unsigned* Qs = (unsigned*)(sm + QS_OFF);   // [112][68] (SCALE pre-folded)
    unsigned* Ks = (unsigned*)(sm + KV_OFF);   // [208][68] (pass 1)
    float*    Vs = sm + KV_OFF;                // [200][72] (pass 3)
    float*    S  = sm + S_OFF;                 // [112][212]

    const int bid = blockIdx.x;
    const int bh = bid >> 1, qb = bid & 1;
    const int b = bh / HEADS, h = bh % HEADS;
    const int q0 = qb * 98;

    const float* Qg = qkv + (size_t)b * SEQ * QKV3 + h * HD;
    const float* Kg = Qg + DIMC;
    const float* Vg = Qg + 2 * DIMC;

    const int tid  = threadIdx.x;
    const int lane = tid & 31;
    const int warp = tid >> 5;
    const int r    = lane >> 2;
    const int tq   = lane & 3;

    // ---- load Q (tf32, pre-scaled by SCALE: exact power of two)
    for (int i = tid; i < 112 * 16; i += 512) {
        int row = i >> 4, c4 = (i & 15) * 4;
        float4 v = make_float4(0.f, 0.f, 0.f, 0.f);
        if (row < 98) v = *(const float4*)(Qg + (size_t)(q0 + row) * QKV3 + c4);
        unsigned* p = &Qs[row * 68 + c4];
        p[0] = f2tf32(v.x * SCALE); p[1] = f2tf32(v.y * SCALE);
        p[2] = f2tf32(v.z * SCALE); p[3] = f2tf32(v.w * SCALE);
    }
    // ---- load K (tf32), rows >= 196 zeroed
    for (int i = tid; i < 208 * 16; i += 512) {
        int row = i >> 4, c4 = (i & 15) * 4;
        float4 v = make_float4(0.f, 0.f, 0.f, 0.f);
        if (row < SEQ) v = *(const float4*)(Kg + (size_t)row * QKV3 + c4);
        unsigned* p = &Ks[row * 68 + c4];
        p[0] = f2tf32(v.x); p[1] = f2tf32(v.y);
        p[2] = f2tf32(v.z); p[3] = f2tf32(v.w);
    }
    __syncthreads();

    // ---- pass 1: S[112][208] = (Q*SCALE) @ K^T
    for (int item = warp; item < 7 * 13; item += 16) {
        int nt = item / 13, mg = item % 13;
        float acc[2][4] = {{0.f,0.f,0.f,0.f},{0.f,0.f,0.f,0.f}};
#pragma unroll
        for (int ks = 0; ks < 8; ks++) {
            int kb = ks * 8;
            unsigned af[4];
            af[0] = Qs[(nt * 16 + r)     * 68 + kb + tq];
            af[1] = Qs[(nt * 16 + r + 8) * 68 + kb + tq];
            af[2] = Qs[(nt * 16 + r)     * 68 + kb + tq + 4];
            af[3] = Qs[(nt * 16 + r + 8) * 68 + kb + tq + 4];
#pragma unroll
            for (int mt = 0; mt < 2; mt++) {
                int cb = mg * 16 + mt * 8;
                unsigned bf[2];
                bf[0] = Ks[(cb + r) * 68 + kb + tq];
                bf[1] = Ks[(cb + r) * 68 + kb + tq + 4];
                mma_tf32(acc[mt], af, bf);
            }
        }
#pragma unroll
        for (int mt = 0; mt < 2; mt++) {
            int c = mg * 16 + mt * 8 + 2 * tq;
            int row = nt * 16 + r;
            S[row * 212 + c]           = acc[mt][0];
            S[row * 212 + c + 1]       = acc[mt][1];
            S[(row + 8) * 212 + c]     = acc[mt][2];
            S[(row + 8) * 212 + c + 1] = acc[mt][3];
        }
    }
    __syncthreads();

    // ---- load V (fp32), overlaps with softmax below
    for (int i = tid; i < 200 * 16; i += 512) {
        int row = i >> 4, c4 = (i & 15) * 4;
        float4 v = make_float4(0.f, 0.f, 0.f, 0.f);
        if (row < SEQ) v = *(const float4*)(Vg + (size_t)row * QKV3 + c4);
        *(float4*)&Vs[row * 72 + c4] = v;
    }

    // ---- pass 2: softmax rows (cols<196) + static_a bias, in place
    for (int row = warp; row < 98; row += 16) {
        float* Sr = S + row * 212;
        float vals[7];
        float mx = -INFINITY;
#pragma unroll
        for (int j = 0; j < 7; j++) {
            int c = lane + 32 * j;
            vals[j] = (c < SEQ) ? Sr[c] : -INFINITY;
            mx = fmaxf(mx, vals[j]);
        }
#pragma unroll
        for (int s = 16; s; s >>= 1) mx = fmaxf(mx, __shfl_xor_sync(0xffffffffu, mx, s));
        float sum = 0.f;
#pragma unroll
        for (int j = 0; j < 7; j++) { vals[j] = __expf(vals[j] - mx); sum += vals[j]; }
#pragma unroll
        for (int s = 16; s; s >>= 1) sum += __shfl_xor_sync(0xffffffffu, sum, s);
        float inv = 1.f / sum;
        const float* ar = sa + ((size_t)h * SEQ + q0 + row) * SEQ;
#pragma unroll
        for (int j = 0; j < 7; j++) {
            int c = lane + 32 * j;
            if (c < SEQ) Sr[c] = vals[j] * inv + ar[c];
        }
    }
    __syncthreads();

    // ---- pass 3: out = S(98x196) @ V(196x64), 3xTF32 split
    float* og = ao + (size_t)b * SEQ * DIMC + h * HD;
    for (int item = warp; item < 7 * 4; item += 16) {
        int nt = item >> 2, cg = item & 3;
        float acc[2][4] = {{0.f,0.f,0.f,0.f},{0.f,0.f,0.f,0.f}};
        for (int ks = 0; ks < 25; ks++) {
            int kb = ks * 8;
            float av[4];
            av[0] = S[(nt * 16 + r)     * 212 + kb + tq];
            av[1] = S[(nt * 16 + r + 8) * 212 + kb + tq];
            av[2] = S[(nt * 16 + r)     * 212 + kb + tq + 4];
            av[3] = S[(nt * 16 + r + 8) * 212 + kb + tq + 4];
            unsigned ahi[4], alo[4];
#pragma unroll
            for (int i = 0; i < 4; i++) {
                ahi[i] = f2tf32(av[i]);
                alo[i] = f2tf32(av[i] - __uint_as_float(ahi[i]));
            }
#pragma unroll
            for (int mt = 0; mt < 2; mt++) {
                int cb = cg * 16 + mt * 8;
                float b0 = Vs[(kb + tq)     * 72 + cb + r];
                float b1 = Vs[(kb + tq + 4) * 72 + cb + r];
                unsigned bhi[2], blo[2];
                bhi[0] = f2tf32(b0); bhi[1] = f2tf32(b1);
                blo[0] = f2tf32(b0 - __uint_as_float(bhi[0]));
                blo[1] = f2tf32(b1 - __uint_as_float(bhi[1]));
                mma_tf32(acc[mt], ahi, bhi);
                mma_tf32(acc[mt], ahi, blo);
                mma_tf32(acc[mt], alo, bhi);
            }
        }
#pragma unroll
        for (int mt = 0; mt < 2; mt++) {
            int c = cg * 16 + mt * 8 + 2 * tq;
            int row = nt * 16 + r;
            if (row < 98)
                *(float2*)(og + (size_t)(q0 + row) * DIMC + c) =
                    make_float2(acc[mt][0], acc[mt][1]);
            if (row + 8 < 98)
                *(float2*)(og + (size_t)(q0 + row + 8) * DIMC + c) =
                    make_float2(acc[mt][2], acc[mt][3]);
        }
    }
}

// ---------------- launch ----------------------------------------------------
extern "C" void kernel_launch(void* const* d_in, const int* in_sizes, int n_in,
                              void* d_out, int out_size)
{
    const float* x     = (const float*)d_in[0];  // [64,196,768]
    const float* Wqkv  = (const float*)d_in[1];  // [768,2304]
    const float* sa    = (const float*)d_in[2];  // [1,12,196,196]
    const float* Wproj = (const float*)d_in[3];  // [768,768]
    const float* bproj = (const float*)d_in[4];  // [768]
    float* out = (float*)d_out;                  // [64,196,768]

    void *p_qkv, *p_ao;
    cudaGetSymbolAddress(&p_qkv, g_qkv);
    cudaGetSymbolAddress(&p_ao, g_ao);
    float* qkv = (float*)p_qkv;
    float* ao  = (float*)p_ao;

    static int smem_set = 0;
    if (!smem_set) {
        cudaFuncSetAttribute(fused_attn_kernel,
                             cudaFuncAttributeMaxDynamicSharedMemorySize,
                             FUSED_SMEM_BYTES);
        cudaFuncSetAttribute(gemm_tf32_kernel,
                             cudaFuncAttributeMaxDynamicSharedMemorySize,
                             GEMM_SMEM_BYTES);
        smem_set = 1;
    }

    // 1) QKV GEMM: [12544,768] @ [768,2304]  (tf32 tensor path, pipelined)
    gemm_tf32_kernel<<<dim3(QKV3 / TBN, BN / TBM), 256, GEMM_SMEM_BYTES>>>(
        x, Wqkv, nullptr, qkv, BN, QKV3, DIMC, 0);
    // 2-4) fused scores + softmax(+static_a) + AV
    fused_attn_kernel<<<BATCH * HEADS * 2, 512, FUSED_SMEM_BYTES>>>(qkv, sa, ao);
    // 5) output projection + bias (tf32 tensor path, pipelined)
    gemm_tf32_kernel<<<dim3(DIMC / TBN, BN / TBM), 256, GEMM_SMEM_BYTES>>>(
        ao, Wproj, bproj, out, BN, DIMC, DIMC, 1);
}

// round 6
// speedup vs baseline: 1.2702x; 1.2702x over previous
#include <cuda_runtime.h>
#include <cuda_bf16.h>
#include <math.h>

#define BATCH 64
#define SEQ   196
#define DIMC  768
#define HEADS 12
#define HD    64
#define QKV3  2304           // 3*DIMC
#define BN    (BATCH*SEQ)    // 12544
#define SCALE 0.125f         // HD^-0.5

// ---------------- scratch (no allocation allowed; __device__ globals) -------
__device__ float g_qkv[(size_t)BATCH * SEQ * QKV3];           // [BN, 2304]
__device__ float g_ao[(size_t)BATCH * SEQ * DIMC];            // [BN, 768]

// ---------------- tf32 helpers ----------------------------------------------
__device__ __forceinline__ unsigned f2tf32(float x) {
    unsigned u;
    asm volatile("cvt.rna.tf32.f32 %0, %1;" : "=r"(u) : "f"(x));
    return u;
}

__device__ __forceinline__ void mma_tf32(float (&d)[4], const unsigned (&a)[4],
                                         const unsigned (&b)[2]) {
    asm volatile(
        "mma.sync.aligned.m16n8k8.row.col.f32.tf32.tf32.f32 "
        "{%0,%1,%2,%3}, {%4,%5,%6,%7}, {%8,%9}, {%0,%1,%2,%3};\n"
        : "+f"(d[0]), "+f"(d[1]), "+f"(d[2]), "+f"(d[3])
        : "r"(a[0]), "r"(a[1]), "r"(a[2]), "r"(a[3]), "r"(b[0]), "r"(b[1]));
}

#define CP_ASYNC16(dst_u32, src_ptr) \
    asm volatile("cp.async.cg.shared.global [%0], [%1], 16;\n" \
                 :: "r"(dst_u32), "l"(src_ptr))
#define CP_COMMIT() asm volatile("cp.async.commit_group;\n" ::: "memory")
#define CP_WAIT1()  asm volatile("cp.async.wait_group 1;\n" ::: "memory")

// ---------------- TF32 GEMM: C[M,N] = A[M,K] @ B[K,N] (+bias) ---------------
// 128x64 block tile, BK=32, 256 threads = 8 warps, warp tile 32x32 (2x4 mma).
// 2-stage cp.async pipeline; raw fp32 in smem, cvt->tf32 at fragment load.
// A group is committed EVERY iteration (possibly empty) so wait_group 1
// always drains the group belonging to the tile about to be computed.
#define TBM 128
#define TBN 64
#define TBK 32
#define AS_STRIDE 36
#define BS_STRIDE 72
#define A_WORDS (TBM * AS_STRIDE)      // 4608
#define B_WORDS (TBK * BS_STRIDE)      // 2304
#define STAGE_WORDS (A_WORDS + B_WORDS)
#define GEMM_SMEM_BYTES (STAGE_WORDS * 2 * 4)   // 55296

__global__ __launch_bounds__(256, 3)
void gemm_tf32_kernel(const float* __restrict__ A, const float* __restrict__ B,
                      const float* __restrict__ bias, float* __restrict__ C,
                      int M, int N, int K, int useBias)
{
    extern __shared__ float gsm[];
    float* Asb[2] = {gsm, gsm + STAGE_WORDS};
    float* Bsb[2] = {gsm + A_WORDS, gsm + STAGE_WORDS + A_WORDS};

    const int tid  = threadIdx.x;
    const int lane = tid & 31;
    const int warp = tid >> 5;
    const int r    = lane >> 2;
    const int tq   = lane & 3;
    const int warpM = (warp & 3) * 32;
    const int warpN = (warp >> 2) * 32;

    const int n0 = blockIdx.x * TBN;
    const int m0 = blockIdx.y * TBM;

    // per-thread copy coordinates
    const int a_row = tid >> 3;             // 0..31 (x4 -> 128 rows)
    const int a_kc  = (tid & 7) * 4;        // 0..28
    const int b_kk  = tid >> 4;             // 0..15 (x2 -> 32 rows)
    const int b_nn  = (tid & 15) * 4;       // 0..60

    unsigned a_dst[2][4], b_dst[2][2];
#pragma unroll
    for (int s = 0; s < 2; s++) {
#pragma unroll
        for (int i = 0; i < 4; i++)
            a_dst[s][i] = (unsigned)__cvta_generic_to_shared(
                &Asb[s][(a_row + i * 32) * AS_STRIDE + a_kc]);
#pragma unroll
        for (int i = 0; i < 2; i++)
            b_dst[s][i] = (unsigned)__cvta_generic_to_shared(
                &Bsb[s][(b_kk + i * 16) * BS_STRIDE + b_nn]);
    }

    const int nTiles = K / TBK;

    // ---- prologue: issue tiles 0 and 1 (2 groups outstanding)
#pragma unroll
    for (int s = 0; s < 2; s++) {
        const int k0 = s * TBK;
#pragma unroll
        for (int i = 0; i < 4; i++)
            CP_ASYNC16(a_dst[s][i], A + (size_t)(m0 + a_row + i * 32) * K + k0 + a_kc);
#pragma unroll
        for (int i = 0; i < 2; i++)
            CP_ASYNC16(b_dst[s][i], B + (size_t)(k0 + b_kk + i * 16) * N + n0 + b_nn);
        CP_COMMIT();
    }

    float acc[2][4][4];
#pragma unroll
    for (int i = 0; i < 2; i++)
#pragma unroll
        for (int j = 0; j < 4; j++)
#pragma unroll
            for (int t = 0; t < 4; t++) acc[i][j][t] = 0.f;

    for (int t = 0; t < nTiles; t++) {
        const int c = t & 1;
        // Invariant: groups for tiles t and t+1 pending (t+1 may be empty).
        // wait_group 1 -> tile t's group complete.
        CP_WAIT1();
        __syncthreads();

        const float* As = Asb[c];
        const float* Bs = Bsb[c];
#pragma unroll
        for (int ks = 0; ks < 4; ks++) {
            int kb = ks * 8;
            unsigned afrag[2][4];
#pragma unroll
            for (int mt = 0; mt < 2; mt++) {
                int rb = warpM + mt * 16;
                afrag[mt][0] = f2tf32(As[(rb + r)     * AS_STRIDE + kb + tq]);
                afrag[mt][1] = f2tf32(As[(rb + r + 8) * AS_STRIDE + kb + tq]);
                afrag[mt][2] = f2tf32(As[(rb + r)     * AS_STRIDE + kb + tq + 4]);
                afrag[mt][3] = f2tf32(As[(rb + r + 8) * AS_STRIDE + kb + tq + 4]);
            }
            unsigned bfrag[4][2];
#pragma unroll
            for (int nt = 0; nt < 4; nt++) {
                int cb = warpN + nt * 8;
                bfrag[nt][0] = f2tf32(Bs[(kb + tq)     * BS_STRIDE + cb + r]);
                bfrag[nt][1] = f2tf32(Bs[(kb + tq + 4) * BS_STRIDE + cb + r]);
            }
#pragma unroll
            for (int mt = 0; mt < 2; mt++)
#pragma unroll
                for (int nt = 0; nt < 4; nt++)
                    mma_tf32(acc[mt][nt], afrag[mt], bfrag[nt]);
        }
        __syncthreads();   // everyone done reading buf c before refilling it

        if (t + 2 < nTiles) {
            const int k0 = (t + 2) * TBK;
#pragma unroll
            for (int i = 0; i < 4; i++)
                CP_ASYNC16(a_dst[c][i], A + (size_t)(m0 + a_row + i * 32) * K + k0 + a_kc);
#pragma unroll
            for (int i = 0; i < 2; i++)
                CP_ASYNC16(b_dst[c][i], B + (size_t)(k0 + b_kk + i * 16) * N + n0 + b_nn);
        }
        CP_COMMIT();   // ALWAYS commit (empty group past the end) — keeps
                       // the wait_group invariant valid on the final tiles
    }

    // ---- epilogue
#pragma unroll
    for (int mt = 0; mt < 2; mt++) {
#pragma unroll
        for (int nt = 0; nt < 4; nt++) {
            int row = m0 + warpM + mt * 16 + r;
            int col = n0 + warpN + nt * 8 + 2 * tq;
            float2 lo = make_float2(acc[mt][nt][0], acc[mt][nt][1]);
            float2 hi = make_float2(acc[mt][nt][2], acc[mt][nt][3]);
            if (useBias) {
                float2 bv = *(const float2*)(bias + col);
                lo.x += bv.x; lo.y += bv.y;
                hi.x += bv.x; hi.y += bv.y;
            }
            *(float2*)(C + (size_t)row * N + col)       = lo;
            *(float2*)(C + (size_t)(row + 8) * N + col) = hi;
        }
    }
}

// ---------------- fused attention: scores + softmax(+bias) + AV -------------
// One block per (b, h, q-half of 98 rows). 512 threads = 16 warps.
#define QS_OFF 0
#define KV_OFF 7616            // 112*68
#define S_OFF  22016           // 7616 + 14400
#define FUSED_SMEM_BYTES (45760 * 4)   // 183040

__global__ __launch_bounds__(512)
void fused_attn_kernel(const float* __restrict__ qkv,
                       const float* __restrict__ sa,
                       float* __restrict__ ao)
{
    extern __shared__ float sm[];
    unsigned* Qs = (unsigned*)(sm + QS_OFF);   // [112][68] (SCALE pre-folded)
    unsigned* Ks = (unsigned*)(sm + KV_OFF);   // [208][68] (pass 1)
    float*    Vs = sm + KV_OFF;                // [200][72] (pass 3)
    float*    S  = sm + S_OFF;                 // [112][212]

    const int bid = blockIdx.x;
    const int bh = bid >> 1, qb = bid & 1;
    const int b = bh / HEADS, h = bh % HEADS;
    const int q0 = qb * 98;

    const float* Qg = qkv + (size_t)b * SEQ * QKV3 + h * HD;
    const float* Kg = Qg + DIMC;
    const float* Vg = Qg + 2 * DIMC;

    const int tid  = threadIdx.x;
    const int lane = tid & 31;
    const int warp = tid >> 5;
    const int r    = lane >> 2;
    const int tq   = lane & 3;

    // ---- load Q (tf32, pre-scaled by SCALE: exact power of two)
    for (int i = tid; i < 112 * 16; i += 512) {
        int row = i >> 4, c4 = (i & 15) * 4;
        float4 v = make_float4(0.f, 0.f, 0.f, 0.f);
        if (row < 98) v = *(const float4*)(Qg + (size_t)(q0 + row) * QKV3 + c4);
        unsigned* p = &Qs[row * 68 + c4];
        p[0] = f2tf32(v.x * SCALE); p[1] = f2tf32(v.y * SCALE);
        p[2] = f2tf32(v.z * SCALE); p[3] = f2tf32(v.w * SCALE);
    }
    // ---- load K (tf32), rows >= 196 zeroed
    for (int i = tid; i < 208 * 16; i += 512) {
        int row = i >> 4, c4 = (i & 15) * 4;
        float4 v = make_float4(0.f, 0.f, 0.f, 0.f);
        if (row < SEQ) v = *(const float4*)(Kg + (size_t)row * QKV3 + c4);
        unsigned* p = &Ks[row * 68 + c4];
        p[0] = f2tf32(v.x); p[1] = f2tf32(v.y);
        p[2] = f2tf32(v.z); p[3] = f2tf32(v.w);
    }
    __syncthreads();

    // ---- pass 1: S[112][208] = (Q*SCALE) @ K^T
    for (int item = warp; item < 7 * 13; item += 16) {
        int nt = item / 13, mg = item % 13;
        float acc[2][4] = {{0.f,0.f,0.f,0.f},{0.f,0.f,0.f,0.f}};
#pragma unroll
        for (int ks = 0; ks < 8; ks++) {
            int kb = ks * 8;
            unsigned af[4];
            af[0] = Qs[(nt * 16 + r)     * 68 + kb + tq];
            af[1] = Qs[(nt * 16 + r + 8) * 68 + kb + tq];
            af[2] = Qs[(nt * 16 + r)     * 68 + kb + tq + 4];
            af[3] = Qs[(nt * 16 + r + 8) * 68 + kb + tq + 4];
#pragma unroll
            for (int mt = 0; mt < 2; mt++) {
                int cb = mg * 16 + mt * 8;
                unsigned bf[2];
                bf[0] = Ks[(cb + r) * 68 + kb + tq];
                bf[1] = Ks[(cb + r) * 68 + kb + tq + 4];
                mma_tf32(acc[mt], af, bf);
            }
        }
#pragma unroll
        for (int mt = 0; mt < 2; mt++) {
            int c = mg * 16 + mt * 8 + 2 * tq;
            int row = nt * 16 + r;
            S[row * 212 + c]           = acc[mt][0];
            S[row * 212 + c + 1]       = acc[mt][1];
            S[(row + 8) * 212 + c]     = acc[mt][2];
            S[(row + 8) * 212 + c + 1] = acc[mt][3];
        }
    }
    __syncthreads();

    // ---- load V (fp32)
    for (int i = tid; i < 200 * 16; i += 512) {
        int row = i >> 4, c4 = (i & 15) * 4;
        float4 v = make_float4(0.f, 0.f, 0.f, 0.f);
        if (row < SEQ) v = *(const float4*)(Vg + (size_t)row * QKV3 + c4);
        *(float4*)&Vs[row * 72 + c4] = v;
    }

    // ---- pass 2: softmax rows (cols<196) + static_a bias, in place
    for (int row = warp; row < 98; row += 16) {
        float* Sr = S + row * 212;
        float vals[7];
        float mx = -INFINITY;
#pragma unroll
        for (int j = 0; j < 7; j++) {
            int c = lane + 32 * j;
            vals[j] = (c < SEQ) ? Sr[c] : -INFINITY;
            mx = fmaxf(mx, vals[j]);
        }
#pragma unroll
        for (int s = 16; s; s >>= 1) mx = fmaxf(mx, __shfl_xor_sync(0xffffffffu, mx, s));
        float sum = 0.f;
#pragma unroll
        for (int j = 0; j < 7; j++) { vals[j] = __expf(vals[j] - mx); sum += vals[j]; }
#pragma unroll
        for (int s = 16; s; s >>= 1) sum += __shfl_xor_sync(0xffffffffu, sum, s);
        float inv = 1.f / sum;
        const float* ar = sa + ((size_t)h * SEQ + q0 + row) * SEQ;
#pragma unroll
        for (int j = 0; j < 7; j++) {
            int c = lane + 32 * j;
            if (c < SEQ) Sr[c] = vals[j] * inv + ar[c];
        }
    }
    __syncthreads();

    // ---- pass 3: out = S(98x196) @ V(196x64), 3xTF32 split
    float* og = ao + (size_t)b * SEQ * DIMC + h * HD;
    for (int item = warp; item < 7 * 4; item += 16) {
        int nt = item >> 2, cg = item & 3;
        float acc[2][4] = {{0.f,0.f,0.f,0.f},{0.f,0.f,0.f,0.f}};
        for (int ks = 0; ks < 25; ks++) {
            int kb = ks * 8;
            float av[4];
            av[0] = S[(nt * 16 + r)     * 212 + kb + tq];
            av[1] = S[(nt * 16 + r + 8) * 212 + kb + tq];
            av[2] = S[(nt * 16 + r)     * 212 + kb + tq + 4];
            av[3] = S[(nt * 16 + r + 8) * 212 + kb + tq + 4];
            unsigned ahi[4], alo[4];
#pragma unroll
            for (int i = 0; i < 4; i++) {
                ahi[i] = f2tf32(av[i]);
                alo[i] = f2tf32(av[i] - __uint_as_float(ahi[i]));
            }
#pragma unroll
            for (int mt = 0; mt < 2; mt++) {
                int cb = cg * 16 + mt * 8;
                float b0 = Vs[(kb + tq)     * 72 + cb + r];
                float b1 = Vs[(kb + tq + 4) * 72 + cb + r];
                unsigned bhi[2], blo[2];
                bhi[0] = f2tf32(b0); bhi[1] = f2tf32(b1);
                blo[0] = f2tf32(b0 - __uint_as_float(bhi[0]));
                blo[1] = f2tf32(b1 - __uint_as_float(bhi[1]));
                mma_tf32(acc[mt], ahi, bhi);
                mma_tf32(acc[mt], ahi, blo);
                mma_tf32(acc[mt], alo, bhi);
            }
        }
#pragma unroll
        for (int mt = 0; mt < 2; mt++) {
            int c = cg * 16 + mt * 8 + 2 * tq;
            int row = nt * 16 + r;
            if (row < 98)
                *(float2*)(og + (size_t)(q0 + row) * DIMC + c) =
                    make_float2(acc[mt][0], acc[mt][1]);
            if (row + 8 < 98)
                *(float2*)(og + (size_t)(q0 + row + 8) * DIMC + c) =
                    make_float2(acc[mt][2], acc[mt][3]);
        }
    }
}

// ---------------- launch ----------------------------------------------------
extern "C" void kernel_launch(void* const* d_in, const int* in_sizes, int n_in,
                              void* d_out, int out_size)
{
    const float* x     = (const float*)d_in[0];  // [64,196,768]
    const float* Wqkv  = (const float*)d_in[1];  // [768,2304]
    const float* sa    = (const float*)d_in[2];  // [1,12,196,196]
    const float* Wproj = (const float*)d_in[3];  // [768,768]
    const float* bproj = (const float*)d_in[4];  // [768]
    float* out = (float*)d_out;                  // [64,196,768]

    void *p_qkv, *p_ao;
    cudaGetSymbolAddress(&p_qkv, g_qkv);
    cudaGetSymbolAddress(&p_ao, g_ao);
    float* qkv = (float*)p_qkv;
    float* ao  = (float*)p_ao;

    static int smem_set = 0;
    if (!smem_set) {
        cudaFuncSetAttribute(fused_attn_kernel,
                             cudaFuncAttributeMaxDynamicSharedMemorySize,
                             FUSED_SMEM_BYTES);
        cudaFuncSetAttribute(gemm_tf32_kernel,
                             cudaFuncAttributeMaxDynamicSharedMemorySize,
                             GEMM_SMEM_BYTES);
        smem_set = 1;
    }

    // 1) QKV GEMM: [12544,768] @ [768,2304]  (tf32, cp.async pipelined)
    gemm_tf32_kernel<<<dim3(QKV3 / TBN, BN / TBM), 256, GEMM_SMEM_BYTES>>>(
        x, Wqkv, nullptr, qkv, BN, QKV3, DIMC, 0);
    // 2-4) fused scores + softmax(+static_a) + AV
    fused_attn_kernel<<<BATCH * HEADS * 2, 512, FUSED_SMEM_BYTES>>>(qkv, sa, ao);
    // 5) output projection + bias (tf32, cp.async pipelined)
    gemm_tf32_kernel<<<dim3(DIMC / TBN, BN / TBM), 256, GEMM_SMEM_BYTES>>>(
        ao, Wproj, bproj, out, BN, DIMC, DIMC, 1);
}